// round 3
// baseline (speedup 1.0000x reference)
#include <cuda_runtime.h>
#include <cuda_bf16.h>
#include <math.h>

// ---------------- problem constants (fixed by metadata) ----------------
#define B_   240
#define S_   64
#define H_   768
#define NH_  12
#define HD_  64
#define L0_  384
#define L1_  128
#define BS0_ 8          // c0 cache batch = 240/30
#define KTOT_ 576       // L0+L1+S
#define OUT_SZ_ 11796480  // 240*64*768
#define INV_SCALE_ 0.125f // 1/sqrt(64)

// Q scratch in head layout [B, NH, S, HD]  (47 MB, static device array: allowed)
__device__ float g_q[OUT_SZ_];

// =====================================================================
// Kernel A: C = A @ W^T + b, output scattered into head layout.
// A: [15360, 768], W: [768, 768] row-major (W^T applied), NT-gemm.
// Tile 64x64, Ktile 16, 256 threads, 4x4 per thread.
// blockIdx.x = batch (row tile == one batch since S=64), .y = head, .z = q/k/v
// =====================================================================
__global__ __launch_bounds__(256)
void qkv_kernel(const float* __restrict__ A,
                const float* __restrict__ Wq, const float* __restrict__ bq,
                const float* __restrict__ Wk, const float* __restrict__ bk,
                const float* __restrict__ Wv, const float* __restrict__ bv,
                float* __restrict__ kdst, float* __restrict__ vdst)
{
    const float* W; const float* bias; float* dst;
    int z = blockIdx.z;
    if (z == 0)      { W = Wq; bias = bq; dst = g_q; }
    else if (z == 1) { W = Wk; bias = bk; dst = kdst; }
    else             { W = Wv; bias = bv; dst = vdst; }

    __shared__ float As[16][68];
    __shared__ float Ws[16][68];

    int t  = threadIdx.x;
    int ty = t >> 4, tx = t & 15;     // 16x16 compute layout
    int lr = t >> 2, lc = t & 3;      // load layout: 64 rows x 4 float4
    int m0 = blockIdx.x * 64;
    int n0 = blockIdx.y * 64;

    float acc[4][4] = {};
    const float* Aptr = A + (size_t)(m0 + lr) * H_ + lc * 4;
    const float* Wptr = W + (size_t)(n0 + lr) * H_ + lc * 4;

    for (int k0 = 0; k0 < H_; k0 += 16) {
        float4 av = *(const float4*)(Aptr + k0);
        float4 wv = *(const float4*)(Wptr + k0);
        __syncthreads();
        As[lc*4+0][lr] = av.x; As[lc*4+1][lr] = av.y;
        As[lc*4+2][lr] = av.z; As[lc*4+3][lr] = av.w;
        Ws[lc*4+0][lr] = wv.x; Ws[lc*4+1][lr] = wv.y;
        Ws[lc*4+2][lr] = wv.z; Ws[lc*4+3][lr] = wv.w;
        __syncthreads();
        #pragma unroll
        for (int kk = 0; kk < 16; kk++) {
            float4 a4 = *(const float4*)&As[kk][ty*4];
            float4 w4 = *(const float4*)&Ws[kk][tx*4];
            float af[4] = {a4.x, a4.y, a4.z, a4.w};
            float wf[4] = {w4.x, w4.y, w4.z, w4.w};
            #pragma unroll
            for (int i = 0; i < 4; i++)
                #pragma unroll
                for (int j = 0; j < 4; j++)
                    acc[i][j] = fmaf(af[i], wf[j], acc[i][j]);
        }
    }

    // epilogue: bias + scatter to head layout [B, NH, S, HD]
    int bi = blockIdx.x;
    int h  = blockIdx.y;
    float bb[4];
    #pragma unroll
    for (int j = 0; j < 4; j++) bb[j] = bias[n0 + tx*4 + j];
    #pragma unroll
    for (int i = 0; i < 4; i++) {
        int s = ty*4 + i;
        float4 o;
        o.x = acc[i][0] + bb[0];
        o.y = acc[i][1] + bb[1];
        o.z = acc[i][2] + bb[2];
        o.w = acc[i][3] + bb[3];
        *(float4*)&dst[((((size_t)bi*NH_ + h)*S_ + s)*HD_) + tx*4] = o;
    }
}

// =====================================================================
// Kernel B: fused attention. One block per (b, h). 256 threads.
// thread t -> q-row = t>>2, quad lane grp = t&3.
// Streams 9 K/V tiles of 64 (c0: 6 tiles [cache b%8], c1: 2, self: 1)
// with online (flash) softmax; ctx accumulated in registers.
// Dynamic smem: Qs/Ks/Vs/Ps, each 64 x 68 floats.
// =====================================================================
#define ROWF 68
__global__ __launch_bounds__(256)
void attn_kernel(const float* __restrict__ mask,
                 const float* __restrict__ c0k, const float* __restrict__ c0v,
                 const float* __restrict__ c1k, const float* __restrict__ c1v,
                 const float* __restrict__ kself, const float* __restrict__ vself,
                 float* __restrict__ out)
{
    extern __shared__ float sm[];
    float* Qs = sm;
    float* Ks = sm + 64*ROWF;
    float* Vs = sm + 2*64*ROWF;
    float* Ps = sm + 3*64*ROWF;

    int b = blockIdx.x;
    int h = blockIdx.y;
    int t = threadIdx.x;
    int row = t >> 2;
    int grp = t & 3;
    int bsi = b & 7;  // b % 8

    // load Q tile
    const float* qp = g_q + (((size_t)b*NH_ + h)*S_)*HD_;
    for (int idx = t; idx < 64*16; idx += 256) {
        int r = idx >> 4, c = idx & 15;
        *(float4*)&Qs[r*ROWF + c*4] = *(const float4*)(qp + r*64 + c*4);
    }

    float m_r = -1e30f, l_r = 0.0f;
    float cx[16];
    #pragma unroll
    for (int i = 0; i < 16; i++) cx[i] = 0.0f;

    const float* mrow = mask + (size_t)b * KTOT_;

    for (int tile = 0; tile < 9; tile++) {
        const float* kp; const float* vp;
        if (tile < 6) {
            size_t base = (((size_t)bsi*NH_ + h)*L0_ + tile*64) * HD_;
            kp = c0k + base; vp = c0v + base;
        } else if (tile < 8) {
            size_t base = (((size_t)b*NH_ + h)*L1_ + (tile-6)*64) * HD_;
            kp = c1k + base; vp = c1v + base;
        } else {
            size_t base = (((size_t)b*NH_ + h)*S_) * HD_;
            kp = kself + base; vp = vself + base;
        }
        __syncthreads();
        for (int idx = t; idx < 64*16; idx += 256) {
            int r = idx >> 4, c = idx & 15;
            *(float4*)&Ks[r*ROWF + c*4] = *(const float4*)(kp + r*64 + c*4);
            *(float4*)&Vs[r*ROWF + c*4] = *(const float4*)(vp + r*64 + c*4);
        }
        __syncthreads();

        // scores: this thread computes 16 k-columns j = grp + 4*jj of its row
        float sa[16];
        #pragma unroll
        for (int jj = 0; jj < 16; jj++) sa[jj] = 0.0f;
        const float* Qrow = Qs + row*ROWF;
        #pragma unroll 4
        for (int kk4 = 0; kk4 < 16; kk4++) {
            float4 q4 = *(const float4*)&Qrow[kk4*4];
            #pragma unroll
            for (int jj = 0; jj < 16; jj++) {
                int j = grp + 4*jj;
                float4 k4 = *(const float4*)&Ks[j*ROWF + kk4*4];
                sa[jj] = fmaf(q4.x, k4.x, sa[jj]);
                sa[jj] = fmaf(q4.y, k4.y, sa[jj]);
                sa[jj] = fmaf(q4.z, k4.z, sa[jj]);
                sa[jj] = fmaf(q4.w, k4.w, sa[jj]);
            }
        }
        int kg0 = tile * 64;
        #pragma unroll
        for (int jj = 0; jj < 16; jj++) {
            int j = grp + 4*jj;
            sa[jj] = sa[jj] * INV_SCALE_ + mrow[kg0 + j];
        }

        // online softmax (per-row stats shared across the 4-lane quad)
        float tm = sa[0];
        #pragma unroll
        for (int jj = 1; jj < 16; jj++) tm = fmaxf(tm, sa[jj]);
        tm = fmaxf(tm, __shfl_xor_sync(0xffffffffu, tm, 1));
        tm = fmaxf(tm, __shfl_xor_sync(0xffffffffu, tm, 2));
        float m_new = fmaxf(m_r, tm);
        float alpha = __expf(m_r - m_new);
        float ts = 0.0f;
        #pragma unroll
        for (int jj = 0; jj < 16; jj++) {
            float p = __expf(sa[jj] - m_new);
            sa[jj] = p;
            ts += p;
        }
        ts += __shfl_xor_sync(0xffffffffu, ts, 1);
        ts += __shfl_xor_sync(0xffffffffu, ts, 2);
        l_r = l_r * alpha + ts;
        m_r = m_new;
        #pragma unroll
        for (int i = 0; i < 16; i++) cx[i] *= alpha;

        // publish probabilities for this row's quad, then accumulate ctx
        #pragma unroll
        for (int jj = 0; jj < 16; jj++)
            Ps[row*ROWF + grp + 4*jj] = sa[jj];
        __syncwarp();

        const float* Prow = Ps + row*ROWF;
        #pragma unroll 4
        for (int j = 0; j < 64; j++) {
            float pv = Prow[j];
            #pragma unroll
            for (int ii = 0; ii < 4; ii++) {
                int vec = grp + 4*ii;            // dims 4*vec .. 4*vec+3
                float4 v4 = *(const float4*)&Vs[j*ROWF + vec*4];
                cx[ii*4+0] = fmaf(pv, v4.x, cx[ii*4+0]);
                cx[ii*4+1] = fmaf(pv, v4.y, cx[ii*4+1]);
                cx[ii*4+2] = fmaf(pv, v4.z, cx[ii*4+2]);
                cx[ii*4+3] = fmaf(pv, v4.w, cx[ii*4+3]);
            }
        }
    }

    // write output: out[b, s=row, h*64 + d]
    float inv_l = 1.0f / l_r;
    #pragma unroll
    for (int ii = 0; ii < 4; ii++) {
        int vec = grp + 4*ii;
        float4 o;
        o.x = cx[ii*4+0] * inv_l;
        o.y = cx[ii*4+1] * inv_l;
        o.z = cx[ii*4+2] * inv_l;
        o.w = cx[ii*4+3] * inv_l;
        *(float4*)&out[((size_t)b*S_ + row)*H_ + h*HD_ + vec*4] = o;
    }
}

// =====================================================================
extern "C" void kernel_launch(void* const* d_in, const int* in_sizes, int n_in,
                              void* d_out, int out_size)
{
    (void)in_sizes; (void)n_in; (void)out_size;
    const float* hs   = (const float*)d_in[0];
    const float* mask = (const float*)d_in[1];
    const float* Wq   = (const float*)d_in[2];
    const float* bq   = (const float*)d_in[3];
    const float* Wk   = (const float*)d_in[4];
    const float* bk   = (const float*)d_in[5];
    const float* Wv   = (const float*)d_in[6];
    const float* bv   = (const float*)d_in[7];
    const float* c0k  = (const float*)d_in[8];
    const float* c0v  = (const float*)d_in[9];
    const float* c1k  = (const float*)d_in[10];
    const float* c1v  = (const float*)d_in[11];

    float* out  = (float*)d_out;
    float* kout = out + OUT_SZ_;
    float* vout = out + 2*(size_t)OUT_SZ_;

    const int smem_bytes = 4 * 64 * ROWF * sizeof(float);  // 69632
    cudaFuncSetAttribute(attn_kernel,
                         cudaFuncAttributeMaxDynamicSharedMemorySize, smem_bytes);

    dim3 g1(B_, NH_, 3);
    qkv_kernel<<<g1, 256>>>(hs, Wq, bq, Wk, bk, Wv, bv, kout, vout);

    dim3 g2(B_, NH_);
    attn_kernel<<<g2, 256, smem_bytes>>>(mask, c0k, c0v, c1k, c1v, kout, vout, out);
}

// round 7
// speedup vs baseline: 1.3962x; 1.3962x over previous
#include <cuda_runtime.h>
#include <cuda_bf16.h>
#include <math.h>

// ---------------- problem constants (fixed by metadata) ----------------
#define B_   240
#define S_   64
#define H_   768
#define NH_  12
#define HD_  64
#define L0_  384
#define L1_  128
#define KTOT_ 576
#define OUT_SZ_ 11796480       // 240*64*768
#define NW_  589824            // 768*768
#define INV_SCALE_ 0.125f

// Static device scratch (allocation-free rule)
__device__ float g_q[OUT_SZ_];                       // Q in head layout
__device__ __nv_bfloat16 g_ah[OUT_SZ_];              // hidden hi
__device__ __nv_bfloat16 g_al[OUT_SZ_];              // hidden lo
__device__ __nv_bfloat16 g_wh[3 * NW_];              // Wq/Wk/Wv hi
__device__ __nv_bfloat16 g_wl[3 * NW_];              // Wq/Wk/Wv lo

// =====================================================================
// Kernel 0: fp32 -> bf16 hi/lo split for A (hidden) and the 3 weights.
// Memory-bound, ~100MB traffic -> ~15us.
// =====================================================================
__global__ __launch_bounds__(256)
void conv_kernel(const float* __restrict__ hs,
                 const float* __restrict__ Wq,
                 const float* __restrict__ Wk,
                 const float* __restrict__ Wv)
{
    const int NA4 = OUT_SZ_ / 4;     // 2949120
    const int NW4 = NW_ / 4;         // 147456
    long i4 = (long)blockIdx.x * 256 + threadIdx.x;   // grid sized exactly

    const float* src;
    __nv_bfloat16 *dh, *dl;
    long off4;
    if (i4 < NA4) {
        src = hs; dh = g_ah; dl = g_al; off4 = i4;
    } else {
        long j = i4 - NA4;
        int w = (int)(j / NW4);
        off4 = j - (long)w * NW4;
        src = (w == 0) ? Wq : (w == 1) ? Wk : Wv;
        dh = g_wh + (size_t)w * NW_;
        dl = g_wl + (size_t)w * NW_;
    }

    float4 x = ((const float4*)src)[off4];
    __nv_bfloat162 h0 = __floats2bfloat162_rn(x.x, x.y);
    __nv_bfloat162 h1 = __floats2bfloat162_rn(x.z, x.w);
    float lx = x.x - __bfloat162float(h0.x);
    float ly = x.y - __bfloat162float(h0.y);
    float lz = x.z - __bfloat162float(h1.x);
    float lw = x.w - __bfloat162float(h1.y);
    __nv_bfloat162 l0 = __floats2bfloat162_rn(lx, ly);
    __nv_bfloat162 l1 = __floats2bfloat162_rn(lz, lw);

    ((__nv_bfloat162*)dh)[off4 * 2    ] = h0;
    ((__nv_bfloat162*)dh)[off4 * 2 + 1] = h1;
    ((__nv_bfloat162*)dl)[off4 * 2    ] = l0;
    ((__nv_bfloat162*)dl)[off4 * 2 + 1] = l1;
}

// =====================================================================
// Kernel A: tensor-core QKV GEMM.  C = A @ W^T + b  (NT, K=768)
// bf16 split: C = Ah*Wh + Ah*Wl + Al*Wh  (fp32 accumulate)
// Block tile 128x128x32, 256 thr = 8 warps, warp tile 64x32 (m16n8k16).
// Smem rows padded to 20 b32 (40 bf16) -> conflict-free fragment loads.
// Output scattered to head layout [B, NH, S, HD].
// =====================================================================
#define SROW 20   // row stride in b32 units

__device__ __forceinline__ void mma16816(float* d, const unsigned* a, const unsigned* b)
{
    asm volatile(
        "mma.sync.aligned.m16n8k16.row.col.f32.bf16.bf16.f32 "
        "{%0,%1,%2,%3}, {%4,%5,%6,%7}, {%8,%9}, {%0,%1,%2,%3};\n"
        : "+f"(d[0]), "+f"(d[1]), "+f"(d[2]), "+f"(d[3])
        : "r"(a[0]), "r"(a[1]), "r"(a[2]), "r"(a[3]), "r"(b[0]), "r"(b[1]));
}

__global__ __launch_bounds__(256, 2)
void qkv_mma_kernel(const float* __restrict__ bq,
                    const float* __restrict__ bk,
                    const float* __restrict__ bv,
                    float* __restrict__ kdst, float* __restrict__ vdst)
{
    int z = blockIdx.z;
    const __nv_bfloat16* Wh = g_wh + (size_t)z * NW_;
    const __nv_bfloat16* Wl = g_wl + (size_t)z * NW_;
    const float* bias = (z == 0) ? bq : (z == 1) ? bk : bv;
    float* dst = (z == 0) ? g_q : (z == 1) ? kdst : vdst;

    __shared__ unsigned sAh[128 * SROW];
    __shared__ unsigned sAl[128 * SROW];
    __shared__ unsigned sWh[128 * SROW];
    __shared__ unsigned sWl[128 * SROW];

    int t    = threadIdx.x;
    int lane = t & 31, wid = t >> 5;
    int wm = wid >> 2, wn = wid & 3;         // 2 x 4 warps
    int g  = lane >> 2, tig = lane & 3;
    int m0 = blockIdx.x * 128;
    int n0 = blockIdx.y * 128;

    int lrow = t >> 1, lhalf = t & 1;        // tile load: 128 rows x 2 halves

    float c[4][4][4];
    #pragma unroll
    for (int i = 0; i < 4; i++)
        #pragma unroll
        for (int j = 0; j < 4; j++)
            #pragma unroll
            for (int k = 0; k < 4; k++) c[i][j][k] = 0.0f;

    const uint4* gAh = (const uint4*)(g_ah + (size_t)(m0 + lrow) * H_);
    const uint4* gAl = (const uint4*)(g_al + (size_t)(m0 + lrow) * H_);
    const uint4* gWh = (const uint4*)(Wh   + (size_t)(n0 + lrow) * H_);
    const uint4* gWl = (const uint4*)(Wl   + (size_t)(n0 + lrow) * H_);

    for (int kt = 0; kt < H_ / 32; kt++) {
        int gi = kt * 4 + lhalf * 2;   // uint4 (=8 bf16) index within row
        uint4 ah0 = gAh[gi], ah1 = gAh[gi + 1];
        uint4 al0 = gAl[gi], al1 = gAl[gi + 1];
        uint4 wh0 = gWh[gi], wh1 = gWh[gi + 1];
        uint4 wl0 = gWl[gi], wl1 = gWl[gi + 1];

        __syncthreads();
        int so = lrow * SROW + lhalf * 8;
        *(uint4*)&sAh[so] = ah0;  *(uint4*)&sAh[so + 4] = ah1;
        *(uint4*)&sAl[so] = al0;  *(uint4*)&sAl[so + 4] = al1;
        *(uint4*)&sWh[so] = wh0;  *(uint4*)&sWh[so + 4] = wh1;
        *(uint4*)&sWl[so] = wl0;  *(uint4*)&sWl[so + 4] = wl1;
        __syncthreads();

        #pragma unroll
        for (int ks = 0; ks < 2; ks++) {
            int ko = ks * 8;
            unsigned af[4][4], wfh[4][2], wfl[4][2];
            #pragma unroll
            for (int am = 0; am < 4; am++) {
                int r = wm * 64 + am * 16 + g;
                af[am][0] = sAh[r * SROW + ko + tig];
                af[am][1] = sAh[(r + 8) * SROW + ko + tig];
                af[am][2] = sAh[r * SROW + ko + tig + 4];
                af[am][3] = sAh[(r + 8) * SROW + ko + tig + 4];
            }
            #pragma unroll
            for (int an = 0; an < 4; an++) {
                int rn = wn * 32 + an * 8 + g;
                wfh[an][0] = sWh[rn * SROW + ko + tig];
                wfh[an][1] = sWh[rn * SROW + ko + tig + 4];
                wfl[an][0] = sWl[rn * SROW + ko + tig];
                wfl[an][1] = sWl[rn * SROW + ko + tig + 4];
            }
            #pragma unroll
            for (int am = 0; am < 4; am++)
                #pragma unroll
                for (int an = 0; an < 4; an++) {
                    mma16816(c[am][an], af[am], wfh[an]);   // Ah*Wh
                    mma16816(c[am][an], af[am], wfl[an]);   // Ah*Wl
                }
            // reload A-lo into the same fragment registers
            #pragma unroll
            for (int am = 0; am < 4; am++) {
                int r = wm * 64 + am * 16 + g;
                af[am][0] = sAl[r * SROW + ko + tig];
                af[am][1] = sAl[(r + 8) * SROW + ko + tig];
                af[am][2] = sAl[r * SROW + ko + tig + 4];
                af[am][3] = sAl[(r + 8) * SROW + ko + tig + 4];
            }
            #pragma unroll
            for (int am = 0; am < 4; am++)
                #pragma unroll
                for (int an = 0; an < 4; an++)
                    mma16816(c[am][an], af[am], wfh[an]);   // Al*Wh
        }
    }

    // Epilogue: bias + scatter to head layout [B, NH, S, HD]
    int batch = blockIdx.x * 2 + wm;          // 64 rows per batch
    #pragma unroll
    for (int an = 0; an < 4; an++) {
        int ncol = wn * 32 + an * 8 + tig * 2;        // 0..126 within block
        int head = blockIdx.y * 2 + (ncol >> 6);
        int d    = ncol & 63;
        float b0 = bias[n0 + ncol];
        float b1 = bias[n0 + ncol + 1];
        #pragma unroll
        for (int am = 0; am < 4; am++) {
            int s = am * 16 + g;
            float* p0 = dst + ((((size_t)batch * NH_ + head) * S_ + s) * HD_) + d;
            float* p1 = dst + ((((size_t)batch * NH_ + head) * S_ + s + 8) * HD_) + d;
            float2 o0 = make_float2(c[am][an][0] + b0, c[am][an][1] + b1);
            float2 o1 = make_float2(c[am][an][2] + b0, c[am][an][3] + b1);
            *(float2*)p0 = o0;
            *(float2*)p1 = o1;
        }
    }
}

// =====================================================================
// Kernel B: fused fp32 attention (unchanged from R2 — L1-bound, next target)
// =====================================================================
#define ROWF 68
__global__ __launch_bounds__(256)
void attn_kernel(const float* __restrict__ mask,
                 const float* __restrict__ c0k, const float* __restrict__ c0v,
                 const float* __restrict__ c1k, const float* __restrict__ c1v,
                 const float* __restrict__ kself, const float* __restrict__ vself,
                 float* __restrict__ out)
{
    extern __shared__ float sm[];
    float* Qs = sm;
    float* Ks = sm + 64*ROWF;
    float* Vs = sm + 2*64*ROWF;
    float* Ps = sm + 3*64*ROWF;

    int b = blockIdx.x;
    int h = blockIdx.y;
    int t = threadIdx.x;
    int row = t >> 2;
    int grp = t & 3;
    int bsi = b & 7;

    const float* qp = g_q + (((size_t)b*NH_ + h)*S_)*HD_;
    for (int idx = t; idx < 64*16; idx += 256) {
        int r = idx >> 4, c = idx & 15;
        *(float4*)&Qs[r*ROWF + c*4] = *(const float4*)(qp + r*64 + c*4);
    }

    float m_r = -1e30f, l_r = 0.0f;
    float cx[16];
    #pragma unroll
    for (int i = 0; i < 16; i++) cx[i] = 0.0f;

    const float* mrow = mask + (size_t)b * KTOT_;

    for (int tile = 0; tile < 9; tile++) {
        const float* kp; const float* vp;
        if (tile < 6) {
            size_t base = (((size_t)bsi*NH_ + h)*L0_ + tile*64) * HD_;
            kp = c0k + base; vp = c0v + base;
        } else if (tile < 8) {
            size_t base = (((size_t)b*NH_ + h)*L1_ + (tile-6)*64) * HD_;
            kp = c1k + base; vp = c1v + base;
        } else {
            size_t base = (((size_t)b*NH_ + h)*S_) * HD_;
            kp = kself + base; vp = vself + base;
        }
        __syncthreads();
        for (int idx = t; idx < 64*16; idx += 256) {
            int r = idx >> 4, c = idx & 15;
            *(float4*)&Ks[r*ROWF + c*4] = *(const float4*)(kp + r*64 + c*4);
            *(float4*)&Vs[r*ROWF + c*4] = *(const float4*)(vp + r*64 + c*4);
        }
        __syncthreads();

        float sa[16];
        #pragma unroll
        for (int jj = 0; jj < 16; jj++) sa[jj] = 0.0f;
        const float* Qrow = Qs + row*ROWF;
        #pragma unroll 4
        for (int kk4 = 0; kk4 < 16; kk4++) {
            float4 q4 = *(const float4*)&Qrow[kk4*4];
            #pragma unroll
            for (int jj = 0; jj < 16; jj++) {
                int j = grp + 4*jj;
                float4 k4 = *(const float4*)&Ks[j*ROWF + kk4*4];
                sa[jj] = fmaf(q4.x, k4.x, sa[jj]);
                sa[jj] = fmaf(q4.y, k4.y, sa[jj]);
                sa[jj] = fmaf(q4.z, k4.z, sa[jj]);
                sa[jj] = fmaf(q4.w, k4.w, sa[jj]);
            }
        }
        int kg0 = tile * 64;
        #pragma unroll
        for (int jj = 0; jj < 16; jj++) {
            int j = grp + 4*jj;
            sa[jj] = sa[jj] * INV_SCALE_ + mrow[kg0 + j];
        }

        float tm = sa[0];
        #pragma unroll
        for (int jj = 1; jj < 16; jj++) tm = fmaxf(tm, sa[jj]);
        tm = fmaxf(tm, __shfl_xor_sync(0xffffffffu, tm, 1));
        tm = fmaxf(tm, __shfl_xor_sync(0xffffffffu, tm, 2));
        float m_new = fmaxf(m_r, tm);
        float alpha = __expf(m_r - m_new);
        float ts = 0.0f;
        #pragma unroll
        for (int jj = 0; jj < 16; jj++) {
            float p = __expf(sa[jj] - m_new);
            sa[jj] = p;
            ts += p;
        }
        ts += __shfl_xor_sync(0xffffffffu, ts, 1);
        ts += __shfl_xor_sync(0xffffffffu, ts, 2);
        l_r = l_r * alpha + ts;
        m_r = m_new;
        #pragma unroll
        for (int i = 0; i < 16; i++) cx[i] *= alpha;

        #pragma unroll
        for (int jj = 0; jj < 16; jj++)
            Ps[row*ROWF + grp + 4*jj] = sa[jj];
        __syncwarp();

        const float* Prow = Ps + row*ROWF;
        #pragma unroll 4
        for (int j = 0; j < 64; j++) {
            float pv = Prow[j];
            #pragma unroll
            for (int ii = 0; ii < 4; ii++) {
                int vec = grp + 4*ii;
                float4 v4 = *(const float4*)&Vs[j*ROWF + vec*4];
                cx[ii*4+0] = fmaf(pv, v4.x, cx[ii*4+0]);
                cx[ii*4+1] = fmaf(pv, v4.y, cx[ii*4+1]);
                cx[ii*4+2] = fmaf(pv, v4.z, cx[ii*4+2]);
                cx[ii*4+3] = fmaf(pv, v4.w, cx[ii*4+3]);
            }
        }
    }

    float inv_l = 1.0f / l_r;
    #pragma unroll
    for (int ii = 0; ii < 4; ii++) {
        int vec = grp + 4*ii;
        float4 o;
        o.x = cx[ii*4+0] * inv_l;
        o.y = cx[ii*4+1] * inv_l;
        o.z = cx[ii*4+2] * inv_l;
        o.w = cx[ii*4+3] * inv_l;
        *(float4*)&out[((size_t)b*S_ + row)*H_ + h*HD_ + vec*4] = o;
    }
}

// =====================================================================
extern "C" void kernel_launch(void* const* d_in, const int* in_sizes, int n_in,
                              void* d_out, int out_size)
{
    (void)in_sizes; (void)n_in; (void)out_size;
    const float* hs   = (const float*)d_in[0];
    const float* mask = (const float*)d_in[1];
    const float* Wq   = (const float*)d_in[2];
    const float* bq   = (const float*)d_in[3];
    const float* Wk   = (const float*)d_in[4];
    const float* bk   = (const float*)d_in[5];
    const float* Wv   = (const float*)d_in[6];
    const float* bv   = (const float*)d_in[7];
    const float* c0k  = (const float*)d_in[8];
    const float* c0v  = (const float*)d_in[9];
    const float* c1k  = (const float*)d_in[10];
    const float* c1v  = (const float*)d_in[11];

    float* out  = (float*)d_out;
    float* kout = out + OUT_SZ_;
    float* vout = out + 2*(size_t)OUT_SZ_;

    const int smem_bytes = 4 * 64 * ROWF * sizeof(float);
    cudaFuncSetAttribute(attn_kernel,
                         cudaFuncAttributeMaxDynamicSharedMemorySize, smem_bytes);

    // 0) fp32 -> bf16 hi/lo split (A and weights)
    int conv_blocks = (OUT_SZ_ / 4 + 3 * (NW_ / 4)) / 256;   // 13248, exact
    conv_kernel<<<conv_blocks, 256>>>(hs, Wq, Wk, Wv);

    // 1) tensor-core QKV projection
    dim3 g1(B_ * S_ / 128, H_ / 128, 3);   // (120, 6, 3)
    qkv_mma_kernel<<<g1, 256>>>(bq, bk, bv, kout, vout);

    // 2) fused attention
    dim3 g2(B_, NH_);
    attn_kernel<<<g2, 256, smem_bytes>>>(mask, c0k, c0v, c1k, c1v, kout, vout, out);
}